// round 8
// baseline (speedup 1.0000x reference)
#include <cuda_runtime.h>
#include <cuda_fp16.h>
#include <cstdint>

#define HID     64
#define SLEN    24
#define ITEMS   128
#define THREADS 256

// Precomputed tables (device globals; no allocation).
__device__ float    g_pre2 [4096];    // fp32 pre2[t][o] = 0.125*embed[t].W1[o][64:128]
__device__ __half   g_pre1h[4096];    // fp16 pre1[t][o] = embed[t].W1[o][0:64] + b1[o]
__device__ unsigned g_w2h  [2048];    // W2 as fp16x2 pairs, row-major [n=64][k=64]
__device__ unsigned g_pre2p[131072];  // fp16x2 pair table: [t1*64+t2][32] (4096 rows x 128B)

// ---------------------------------------------------------------------------
// Precompute 1: one warp per (t,o); lanes split K=64, shfl-reduce.
// First 2048 flat threads also convert W2 -> fp16x2.
// ---------------------------------------------------------------------------
__global__ void precompute_kernel(const float* __restrict__ embed_W,
                                  const float* __restrict__ W1,
                                  const float* __restrict__ b1,
                                  const float* __restrict__ W2)
{
    int warpId = (blockIdx.x * blockDim.x + threadIdx.x) >> 5;   // 0..4095
    int lane   = threadIdx.x & 31;
    int t = warpId >> 6;
    int o = warpId & 63;
    const float* e   = embed_W + t * HID;
    const float* w1o = W1 + o * (2 * HID);
    float e1 = e[lane], e2 = e[lane + 32];
    float s1 = e1 * w1o[lane]      + e2 * w1o[lane + 32];
    float s2 = e1 * w1o[64 + lane] + e2 * w1o[96 + lane];
#pragma unroll
    for (int d = 16; d > 0; d >>= 1) {
        s1 += __shfl_xor_sync(0xffffffffu, s1, d);
        s2 += __shfl_xor_sync(0xffffffffu, s2, d);
    }
    if (lane == 0) {
        g_pre1h[warpId] = __float2half(s1 + b1[o]);
        g_pre2 [warpId] = s2 * 0.125f;
    }
    int flat = blockIdx.x * blockDim.x + threadIdx.x;
    if (flat < 2048) {
        int n = flat >> 5, kk = flat & 31;
        __half2 h2 = __floats2half2_rn(W2[n * 64 + 2 * kk], W2[n * 64 + 2 * kk + 1]);
        g_w2h[flat] = *(unsigned*)&h2;
    }
}

// ---------------------------------------------------------------------------
// Precompute 2: pair-sum table. flat thread -> (pair, dim-pair).
// pre2p[t1*64+t2][2d..2d+1] = fp16(pre2[t1][2d]+pre2[t2][2d]) , fp16(...+1)
// ---------------------------------------------------------------------------
__global__ void pair_kernel()
{
    int flat = blockIdx.x * blockDim.x + threadIdx.x;      // 0..131071
    int pair = flat >> 5;
    int dp   = flat & 31;
    int t1 = pair >> 6, t2 = pair & 63;
    float a0 = g_pre2[t1 * 64 + 2 * dp]     + g_pre2[t2 * 64 + 2 * dp];
    float a1 = g_pre2[t1 * 64 + 2 * dp + 1] + g_pre2[t2 * 64 + 2 * dp + 1];
    __half2 h2 = __floats2half2_rn(a0, a1);
    g_pre2p[flat] = *(unsigned*)&h2;
}

// ---------------------------------------------------------------------------
// Main kernel. smem layout (bytes):
//   [0,8192)       s_pre1h fp16 [64][64]        (128B rows)
//   [8192,17408)   s_w2    fp16 [64 rows][72]   (144B padded rows)
//   [17408,35840)  s_H     fp16 [128 rows][72]  (144B padded rows)
//   [35840,36096)  s_b2    fp32 [64]
// ---------------------------------------------------------------------------
#define OFF_PRE1H  0
#define OFF_W2H    8192
#define OFF_H      17408
#define OFF_B2     35840
#define SMEM_TOTAL 36096
#define ROWB       144          // padded row stride in bytes

__global__ __launch_bounds__(THREADS, 3)
void lru_main(const int*   __restrict__ seqs,
              const int*   __restrict__ query_tok,
              const float* __restrict__ b2,
              float*       __restrict__ out,
              int B)
{
    extern __shared__ char sm[];
    unsigned* s_pre1h = (unsigned*)(sm + OFF_PRE1H);
    char*     s_w2    = sm + OFF_W2H;
    char*     s_H     = sm + OFF_H;
    float*    s_b2    = (float*)(sm + OFF_B2);

    const int tid  = threadIdx.x;
    const int warp = tid >> 5;
    const int lane = tid & 31;
    const int blockBase = blockIdx.x * ITEMS;

    // ---- index loads first (overlap GMEM latency with table staging) ----
    // pa = pair01 | pair23<<12 ; pb = pair45 | pair67<<12 | q<<24
    unsigned pa = 0, pb = 0;
    {
        int it = blockBase + warp * 16 + lane;
        if (lane < 16 && it < B) {
            const int* row = seqs + (size_t)it * SLEN;   // 96B stride: row+16 is 16B aligned
            int  t0  = row[15];
            int4 t14 = *(const int4*)(row + 16);
            int2 t56 = *(const int2*)(row + 20);
            int  t7  = row[22];
            int  tq  = query_tok[it];
            pa = (unsigned)(t0 * 64 + t14.x) | ((unsigned)(t14.y * 64 + t14.z) << 12);
            pb = (unsigned)(t14.w * 64 + t56.x)
               | ((unsigned)(t56.y * 64 + t7) << 12)
               | ((unsigned)tq << 24);
        }
    }

    // ---- stage tables into smem ----
    {
        const uint2* s1 = (const uint2*)g_pre1h;
#pragma unroll
        for (int i = tid; i < 1024; i += THREADS) ((uint2*)s_pre1h)[i] = s1[i];
#pragma unroll
        for (int i = tid; i < 2048; i += THREADS) {
            int n = i >> 5, kk = i & 31;
            *(unsigned*)(s_w2 + n * ROWB + kk * 4) = g_w2h[i];
        }
        if (tid < 16) ((float4*)s_b2)[tid] = ((const float4*)b2)[tid];
    }
    __syncthreads();

    // ---- gather: warp w owns items [16w, 16w+16) == its own M-tile rows ----
    // z = pre1h[q] (smem) + 4 pair-sum rows (gmem/L2), accumulated in fp32.
#pragma unroll 2
    for (int m = 0; m < 16; m++) {
        unsigned am = __shfl_sync(0xffffffffu, pa, m);
        unsigned bm = __shfl_sync(0xffffffffu, pb, m);
        // issue the 4 independent LDGs up front (L2 hits; MLP hides latency)
        unsigned u0 = __ldg(&g_pre2p[((am & 0xFFFu) << 5) + lane]);
        unsigned u1 = __ldg(&g_pre2p[((am >> 12)    << 5) + lane]);
        unsigned u2 = __ldg(&g_pre2p[((bm & 0xFFFu) << 5) + lane]);
        unsigned u3 = __ldg(&g_pre2p[(((bm >> 12) & 0xFFFu) << 5) + lane]);
        unsigned uq = s_pre1h[((bm >> 24) << 5) + lane];

        float2 z  = __half22float2(*(const __half2*)&uq);
        float2 v0 = __half22float2(*(const __half2*)&u0);
        float2 v1 = __half22float2(*(const __half2*)&u1);
        float2 v2 = __half22float2(*(const __half2*)&u2);
        float2 v3 = __half22float2(*(const __half2*)&u3);
        z.x += v0.x + v1.x; z.y += v0.y + v1.y;
        z.x += v2.x + v3.x; z.y += v2.y + v3.y;
        z.x = fmaxf(z.x, 0.f);
        z.y = fmaxf(z.y, 0.f);
        unsigned packed;                       // lo = z.x (col 2*lane), hi = z.y
        asm("cvt.rn.f16x2.f32 %0, %1, %2;" : "=r"(packed) : "f"(z.y), "f"(z.x));
        // row = warp*16+m, cols [2*lane, 2*lane+1]; bank (36r+lane)%32 conflict-free
        *(unsigned*)(s_H + (warp * 16 + m) * ROWB + lane * 4) = packed;
    }
    __syncwarp();   // warp's own H rows visible to all its lanes

    // ---- MMA: warp computes rows [16w,16w+16) x all 64 cols via 8n x 4k HMMA ----
    const int r = lane >> 2;        // 0..7
    const int c = lane & 3;         // 0..3
    float acc[8][4];
#pragma unroll
    for (int nt = 0; nt < 8; nt++) {
        int col = 8 * nt + 2 * c;
        acc[nt][0] = s_b2[col];
        acc[nt][1] = s_b2[col + 1];
        acc[nt][2] = acc[nt][0];
        acc[nt][3] = acc[nt][1];
    }
    const char* Ab = s_H + (warp * 16 + r) * ROWB + 4 * c;
#pragma unroll
    for (int kt = 0; kt < 4; kt++) {
        unsigned a0 = *(const unsigned*)(Ab + 32 * kt);              // row r,   k0
        unsigned a1 = *(const unsigned*)(Ab + 8 * ROWB + 32 * kt);   // row r+8, k0
        unsigned a2 = *(const unsigned*)(Ab + 16 + 32 * kt);         // row r,   k0+8
        unsigned a3 = *(const unsigned*)(Ab + 8 * ROWB + 16 + 32 * kt);
#pragma unroll
        for (int nt = 0; nt < 8; nt++) {
            const char* Bb = s_w2 + (8 * nt + r) * ROWB + 4 * c + 32 * kt;
            unsigned b0 = *(const unsigned*)(Bb);        // n, k0..k0+1
            unsigned b1 = *(const unsigned*)(Bb + 16);   // n, k0+8..k0+9
            asm volatile(
                "mma.sync.aligned.m16n8k16.row.col.f32.f16.f16.f32 "
                "{%0,%1,%2,%3}, {%4,%5,%6,%7}, {%8,%9}, {%0,%1,%2,%3};"
                : "+f"(acc[nt][0]), "+f"(acc[nt][1]), "+f"(acc[nt][2]), "+f"(acc[nt][3])
                : "r"(a0), "r"(a1), "r"(a2), "r"(a3), "r"(b0), "r"(b1));
        }
    }

    // ---- epilogue: direct float2 stores (L2 merges into full lines) ----
    {
        int item0 = blockBase + warp * 16 + r;
        int item1 = item0 + 8;
        float* o0 = out + (size_t)item0 * HID + 2 * c;
        float* o1 = out + (size_t)item1 * HID + 2 * c;
        if (item1 < B) {
#pragma unroll
            for (int nt = 0; nt < 8; nt++) {
                *(float2*)(o0 + 8 * nt) = make_float2(acc[nt][0], acc[nt][1]);
                *(float2*)(o1 + 8 * nt) = make_float2(acc[nt][2], acc[nt][3]);
            }
        } else {
#pragma unroll
            for (int nt = 0; nt < 8; nt++) {
                if (item0 < B) *(float2*)(o0 + 8 * nt) = make_float2(acc[nt][0], acc[nt][1]);
                if (item1 < B) *(float2*)(o1 + 8 * nt) = make_float2(acc[nt][2], acc[nt][3]);
            }
        }
    }
}

extern "C" void kernel_launch(void* const* d_in, const int* in_sizes, int n_in,
                              void* d_out, int out_size)
{
    const int*   seqs   = (const int*)  d_in[0];
    const int*   query  = (const int*)  d_in[1];
    const float* embedW = (const float*)d_in[2];
    const float* W1     = (const float*)d_in[3];
    const float* b1     = (const float*)d_in[4];
    const float* W2     = (const float*)d_in[5];
    const float* b2     = (const float*)d_in[6];
    float*       out    = (float*)d_out;

    const int B = in_sizes[0] / SLEN;

    precompute_kernel<<<512, 256>>>(embedW, W1, b1, W2);
    pair_kernel<<<512, 256>>>();

    cudaFuncSetAttribute(lru_main, cudaFuncAttributeMaxDynamicSharedMemorySize, SMEM_TOTAL);
    const int grid = (B + ITEMS - 1) / ITEMS;
    lru_main<<<grid, THREADS, SMEM_TOTAL>>>(seqs, query, b2, out, B);
}